// round 9
// baseline (speedup 1.0000x reference)
#include <cuda_runtime.h>
#include <math.h>

// Problem constants: x [T=8, B=32, C=128, H=32, W=32]
#define T_STEPS 8
#define BATCH   32
#define CH      128
#define PLANE   1024                     // 32*32
#define NIMG    (T_STEPS * BATCH)        // 256
#define NELEM   (BATCH * CH * PLANE)     // 4,194,304
#define TOTAL   (T_STEPS * NELEM)        // 33,554,432
#define SRS     36                       // padded-plane row stride (floats)

typedef unsigned long long ull;

// Scratch ping-pong buffers (no cudaMalloc allowed).
__device__ float g_spk[TOTAL];
__device__ float g_y[TOTAL];

// Packed fp32x2 FMA (Blackwell FFMA2 — only reachable via PTX).
__device__ __forceinline__ void fma2(ull& acc, ull a, ull b) {
    asm("fma.rn.f32x2 %0, %1, %2, %0;" : "+l"(acc) : "l"(a), "l"(b));
}
__device__ __forceinline__ void unpk(ull a, float& lo, float& hi) {
    asm("mov.b64 {%0, %1}, %2;" : "=f"(lo), "=f"(hi) : "l"(a));
}

// ---------------------------------------------------------------------------
// Multi-step IF neuron, float4-vectorized: v += x_t; s = (v>=1); v *= (1-s)
// ---------------------------------------------------------------------------
__global__ void if_kernel(const float4* __restrict__ in, float4* __restrict__ out) {
    int idx = blockIdx.x * blockDim.x + threadIdx.x;   // NELEM/4 threads
    float v[4] = {0.f, 0.f, 0.f, 0.f};
#pragma unroll
    for (int t = 0; t < T_STEPS; ++t) {
        float4 x = in[(size_t)t * (NELEM / 4) + idx];
        float s[4];
        v[0] += x.x; v[1] += x.y; v[2] += x.z; v[3] += x.w;
#pragma unroll
        for (int j = 0; j < 4; ++j) {
            s[j] = (v[j] >= 1.0f) ? 1.0f : 0.0f;
            v[j] *= (1.0f - s[j]);
        }
        out[(size_t)t * (NELEM / 4) + idx] = make_float4(s[0], s[1], s[2], s[3]);
    }
}

// ---------------------------------------------------------------------------
// 3x3 conv (pad 1) + BN fused, FFMA2.
// Grid: (cog, tb). Block 256, 2 CTAs/SM.
// Dual shifted SMEM copies: P0[j]=padded[j], P1[j]=padded[j+1] -> all three
// horizontal tap-pairs are aligned LDS.64 (no repack MOVs).
// 2 input channels per buffer -> 64 barriers. Weights padded to 80B/co for
// LDS.128 broadcast loads.
// ---------------------------------------------------------------------------
__global__ void __launch_bounds__(256, 2)
conv_bn_kernel(const float* __restrict__ in, const float* __restrict__ wgt,
               const float* __restrict__ gamma, const float* __restrict__ beta,
               const float* __restrict__ mean,  const float* __restrict__ var,
               float* __restrict__ out) {
    __shared__ __align__(16) float  sP0[2][2][34 * SRS];   // [buf][slot]
    __shared__ __align__(16) float  sP1[2][2][34 * SRS];
    __shared__ __align__(16) float2 swt[2][2][8][10];      // [buf][slot][co][tap(9)+pad]

    const int cobase = blockIdx.x * 8;
    const int tb     = blockIdx.y;
    const int tid    = threadIdx.x;
    const int sp     = tid & 127;
    const int ch     = tid >> 7;            // co-half: 0 or 1
    const int h0     = (sp >> 4) * 4;       // first output row (0,4,...,28)
    const int c0     = (sp & 15) * 2;       // even output column
    const int srow   = (tid >> 3) + 1;      // staging padded row 1..32
    const int scol4  = (tid & 7) * 4;       // staging input col base 0,4,...,28

    // Zero both plane arrays once (borders must be 0).
    for (int i = tid; i < 2 * 2 * 34 * SRS; i += 256) {
        ((float*)sP0)[i] = 0.f;
        ((float*)sP1)[i] = 0.f;
    }
    __syncthreads();

    const float* ipbase = in + (size_t)tb * CH * PLANE;

    // Stage ci = 0,1 into buffer 0.
#pragma unroll
    for (int s = 0; s < 2; ++s) {
        float4 v = ((const float4*)(ipbase + (size_t)s * PLANE))[tid];
        float* p0 = &sP0[0][s][srow * SRS + scol4 + 1];   // P0[j] = padded[j]
        p0[0] = v.x; p0[1] = v.y; p0[2] = v.z; p0[3] = v.w;
        *(float4*)&sP1[0][s][srow * SRS + scol4] = v;     // P1[j] = padded[j+1]
    }
    if (tid < 144) {
        int s = (tid >= 72) ? 1 : 0, id = tid - 72 * s;
        int co = id / 9, k = id - co * 9;
        float w = wgt[((size_t)(cobase + co) * CH + s) * 9 + k];
        swt[0][s][co][k] = make_float2(w, w);
    }
    __syncthreads();

    ull acc[4][4];
#pragma unroll
    for (int pr = 0; pr < 4; ++pr)
#pragma unroll
        for (int c = 0; c < 4; ++c) acc[pr][c] = 0ull;

    const int bi = (h0 * SRS + c0) >> 1;    // ull index of window base

    for (int it = 0; it < 64; ++it) {
        const int buf = it & 1;

        // Prefetch next channel pair (latency overlaps compute below).
        float4 vn0, vn1; float wn = 0.f;
        const bool more = (it < 63);
        if (more) {
            const float* np = ipbase + (size_t)(it * 2 + 2) * PLANE;
            vn0 = ((const float4*)np)[tid];
            vn1 = ((const float4*)(np + PLANE))[tid];
            if (tid < 144) {
                int s = (tid >= 72) ? 1 : 0, id = tid - 72 * s;
                int co = id / 9, k = id - co * 9;
                wn = wgt[((size_t)(cobase + co) * CH + (it * 2 + 2 + s)) * 9 + k];
            }
        }

#pragma unroll
        for (int s = 0; s < 2; ++s) {
            const ull* P0 = (const ull*)sP0[buf][s];
            const ull* P1 = (const ull*)sP1[buf][s];
            ull A[6], Bv[6], M[6];
#pragma unroll
            for (int r = 0; r < 6; ++r) {
                A[r]  = P0[bi + r * (SRS / 2)];       // cols c0,   c0+1
                Bv[r] = P0[bi + r * (SRS / 2) + 1];   // cols c0+2, c0+3
                M[r]  = P1[bi + r * (SRS / 2)];       // cols c0+1, c0+2
            }
            const float2* wbase = &swt[buf][s][ch * 4][0];
#pragma unroll
            for (int co = 0; co < 4; ++co) {
                const ulonglong2* wq = (const ulonglong2*)(wbase + (size_t)co * 10);
                ulonglong2 q0 = wq[0], q1 = wq[1], q2 = wq[2], q3 = wq[3];
                ull w8 = *(const ull*)(wbase + (size_t)co * 10 + 8);
#pragma unroll
                for (int pr = 0; pr < 4; ++pr) {
                    fma2(acc[pr][co], A[pr + 0],  q0.x);
                    fma2(acc[pr][co], M[pr + 0],  q0.y);
                    fma2(acc[pr][co], Bv[pr + 0], q1.x);
                    fma2(acc[pr][co], A[pr + 1],  q1.y);
                    fma2(acc[pr][co], M[pr + 1],  q2.x);
                    fma2(acc[pr][co], Bv[pr + 1], q2.y);
                    fma2(acc[pr][co], A[pr + 2],  q3.x);
                    fma2(acc[pr][co], M[pr + 2],  q3.y);
                    fma2(acc[pr][co], Bv[pr + 2], w8);
                }
            }
        }

        // Commit prefetched pair to the other buffer.
        if (more) {
            const int nb = buf ^ 1;
            {
                float* p0 = &sP0[nb][0][srow * SRS + scol4 + 1];
                p0[0] = vn0.x; p0[1] = vn0.y; p0[2] = vn0.z; p0[3] = vn0.w;
                *(float4*)&sP1[nb][0][srow * SRS + scol4] = vn0;
            }
            {
                float* p0 = &sP0[nb][1][srow * SRS + scol4 + 1];
                p0[0] = vn1.x; p0[1] = vn1.y; p0[2] = vn1.z; p0[3] = vn1.w;
                *(float4*)&sP1[nb][1][srow * SRS + scol4] = vn1;
            }
            if (tid < 144) {
                int s = (tid >= 72) ? 1 : 0, id = tid - 72 * s;
                int co = id / 9, k = id - co * 9;
                swt[nb][s][co][k] = make_float2(wn, wn);
            }
        }
        __syncthreads();
    }

    // Fused BN epilogue: y*inv + (beta - mean*inv)
#pragma unroll
    for (int co = 0; co < 4; ++co) {
        const int cg  = cobase + ch * 4 + co;
        const float invd = gamma[cg] / sqrtf(var[cg] + 1e-5f);
        const float bias = beta[cg] - mean[cg] * invd;
        float* op = out + ((size_t)tb * CH + cg) * PLANE;
#pragma unroll
        for (int pr = 0; pr < 4; ++pr) {
            float lo, hi;
            unpk(acc[pr][co], lo, hi);
            *(float2*)&op[(h0 + pr) * 32 + c0] = make_float2(lo * invd + bias, hi * invd + bias);
        }
    }
}

// ---------------------------------------------------------------------------
// Pipeline: if1(x)->spk ; conv1(spk)->y ; if2(y)->spk ; conv2(spk)->out
// ---------------------------------------------------------------------------
extern "C" void kernel_launch(void* const* d_in, const int* in_sizes, int n_in,
                              void* d_out, int out_size) {
    const float* x  = (const float*)d_in[0];
    const float* w1 = (const float*)d_in[1];
    const float* g1 = (const float*)d_in[2];
    const float* b1 = (const float*)d_in[3];
    const float* m1 = (const float*)d_in[4];
    const float* v1 = (const float*)d_in[5];
    const float* w2 = (const float*)d_in[6];
    const float* g2 = (const float*)d_in[7];
    const float* b2 = (const float*)d_in[8];
    const float* m2 = (const float*)d_in[9];
    const float* v2 = (const float*)d_in[10];
    float* out = (float*)d_out;

    float *spk = nullptr, *y = nullptr;
    cudaGetSymbolAddress((void**)&spk, g_spk);
    cudaGetSymbolAddress((void**)&y,   g_y);

    const int ifBlocks = (NELEM / 4 + 255) / 256;
    dim3 cgrid(CH / 8, NIMG);   // co-group fast -> same-image blocks co-resident

    if_kernel<<<ifBlocks, 256>>>((const float4*)x, (float4*)spk);
    conv_bn_kernel<<<cgrid, 256>>>(spk, w1, g1, b1, m1, v1, y);
    if_kernel<<<ifBlocks, 256>>>((const float4*)y, (float4*)spk);
    conv_bn_kernel<<<cgrid, 256>>>(spk, w2, g2, b2, m2, v2, out);
}

// round 12
// speedup vs baseline: 1.5293x; 1.5293x over previous
#include <cuda_runtime.h>
#include <cuda_bf16.h>
#include <math.h>
#include <stdint.h>

#define T_STEPS 8
#define CH      128
#define PLANE   1024
#define NELEM   (32 * CH * PLANE)          // 4,194,304
#define TOTAL   (T_STEPS * NELEM)          // 33,554,432
#define EPS     1e-5f
#define DELTA   3e-3f                      // IF2 near-threshold flag window
#define FLAGCAP (1 << 21)

// Scratch (no cudaMalloc allowed)
__device__ __align__(16) __nv_bfloat16 g_spk[TOTAL];           // IF1 spikes [p][tb][ci]
__device__ __align__(16) __nv_bfloat16 g_spk2[TOTAL];          // IF2 spikes [p][tb][ci]
__device__ __align__(16) float         g_mid[TOTAL];           // conv out [p][tb][co]
__device__ __align__(16) __nv_bfloat16 g_w1p[27 * 128 * 128];  // conv1 3-split [k*3+s][co][ci]
__device__ __align__(16) __nv_bfloat16 g_w2p[18 * 128 * 128];  // conv2 2-split [k*2+s][co][ci]
__device__ unsigned int g_flags[FLAGCAP];
__device__ unsigned int g_nflag;

// ------------------------- helpers -----------------------------------------
__device__ __forceinline__ uint32_t smem_u32(const void* p) {
    uint32_t a;
    asm("{ .reg .u64 t; cvta.to.shared.u64 t, %1; cvt.u32.u64 %0, t; }" : "=r"(a) : "l"(p));
    return a;
}
__device__ __forceinline__ void ldsm4(uint32_t* r, uint32_t a) {
    asm volatile("ldmatrix.sync.aligned.m8n8.x4.shared.b16 {%0,%1,%2,%3}, [%4];"
                 : "=r"(r[0]), "=r"(r[1]), "=r"(r[2]), "=r"(r[3]) : "r"(a));
}
__device__ __forceinline__ void mma16816(float* d, const uint32_t* a, uint32_t b0, uint32_t b1) {
    asm volatile(
        "mma.sync.aligned.m16n8k16.row.col.f32.bf16.bf16.f32 "
        "{%0,%1,%2,%3}, {%4,%5,%6,%7}, {%8,%9}, {%0,%1,%2,%3};"
        : "+f"(d[0]), "+f"(d[1]), "+f"(d[2]), "+f"(d[3])
        : "r"(a[0]), "r"(a[1]), "r"(a[2]), "r"(a[3]), "r"(b0), "r"(b1));
}
// XOR-swizzled offset in a [rows x 128ci] bf16 tile (256B rows, 16B chunks)
__device__ __forceinline__ uint32_t soff(int row, int ch) {
    return (uint32_t)(row * 256 + ((ch ^ (row & 7)) << 4));
}

// ------------------------- weight split ------------------------------------
template<int S>
__global__ void wprep_kernel(const float* __restrict__ w, __nv_bfloat16* __restrict__ wp) {
    int idx = blockIdx.x * 256 + threadIdx.x;          // 9*128*128
    if (idx >= 9 * 128 * 128) return;
    int ci = idx & 127, co = (idx >> 7) & 127, k = idx >> 14;
    float v = w[((size_t)co * 128 + ci) * 9 + k];
#pragma unroll
    for (int s = 0; s < S; s++) {
        __nv_bfloat16 h = __float2bfloat16(v);
        wp[(((size_t)k * S + s) * 128 + co) * 128 + ci] = h;
        v -= __bfloat162float(h);
    }
}

// ------------------------- IF1: NCHW fp32 -> [p][tb][ci] bf16 ---------------
__global__ void if1_kernel(const float* __restrict__ x, __nv_bfloat16* __restrict__ out) {
    __shared__ __nv_bfloat16 sm[32][34];
    const int p0 = blockIdx.x * 32, ci0 = blockIdx.y * 32, b = blockIdx.z;
    const int i = threadIdx.x >> 5, j = threadIdx.x & 31;
    const float* xp = x + ((size_t)b * CH + ci0 + i) * PLANE + p0 + j;
    float v = 0.f;
#pragma unroll
    for (int t = 0; t < T_STEPS; t++) {
        v += xp[(size_t)t * NELEM];
        float s = (v >= 1.f) ? 1.f : 0.f;
        v *= (1.f - s);
        __syncthreads();
        sm[j][i] = __float2bfloat16(s);
        __syncthreads();
        out[((size_t)(p0 + i) * 256 + t * 32 + b) * 128 + ci0 + j] = sm[i][j];
    }
}

// ------------------------- IF2 + near-threshold flagging --------------------
__global__ void zero_flag_kernel() {
    if (threadIdx.x == 0 && blockIdx.x == 0) g_nflag = 0;
}
__global__ void if2_flag_kernel(const float* __restrict__ in, __nv_bfloat16* __restrict__ out) {
    size_t idx = (size_t)blockIdx.x * 256 + threadIdx.x;   // p*32*128
    int co = (int)(idx & 127);
    int b  = (int)((idx >> 7) & 31);
    size_t p = idx >> 12;
    float v = 0.f;
    bool near = false;
#pragma unroll
    for (int t = 0; t < T_STEPS; t++) {
        size_t off = (p * 256 + (size_t)t * 32 + b) * 128 + co;
        v += in[off];
        near |= (fabsf(v - 1.f) < DELTA);
        float s = (v >= 1.f) ? 1.f : 0.f;
        v *= (1.f - s);
        out[off] = __float2bfloat16(s);
    }
    if (near) {
        unsigned int id = atomicAdd(&g_nflag, 1u);
        if (id < FLAGCAP) g_flags[id] = ((unsigned)p << 12) | ((unsigned)b << 7) | (unsigned)co;
    }
}

// ------------------------- flip correction ----------------------------------
// One warp per flagged neuron. Lanes 0-7 recompute conv1+BN for t=lane in the
// exact FFMA2-kernel order (ci ascending, taps row-major, same BN source text);
// then all lanes rescan and lane t rewrites spike_t.
__global__ void __launch_bounds__(128)
fix_kernel(const __nv_bfloat16* __restrict__ spk, const float* __restrict__ wgt,
           const float* __restrict__ gamma, const float* __restrict__ beta,
           const float* __restrict__ mean,  const float* __restrict__ var,
           __nv_bfloat16* __restrict__ out) {
    const unsigned int n = min(g_nflag, (unsigned)FLAGCAP);
    const int lane = threadIdx.x & 31;
    const int gw = (blockIdx.x * 128 + threadIdx.x) >> 5;   // global warp id
    for (unsigned int i = gw; i < n; i += 4096 * 4) {
        const unsigned int f = g_flags[i];
        const int co = f & 127, b = (f >> 7) & 31, p = f >> 12;
        const int h = p >> 5, w = p & 31;
        float y = 0.f;
        if (lane < 8) {
            const int t = lane;
            float acc = 0.f;
            for (int ci = 0; ci < 128; ci++) {
                const float* wk = wgt + ((size_t)co * 128 + ci) * 9;
#pragma unroll
                for (int ky = 0; ky < 3; ky++) {
                    const int yy = h + ky - 1;
                    if (yy < 0 || yy >= 32) continue;
#pragma unroll
                    for (int kx = 0; kx < 3; kx++) {
                        const int xx = w + kx - 1;
                        if (xx < 0 || xx >= 32) continue;
                        float sp = __bfloat162float(
                            spk[((size_t)(yy * 32 + xx) * 256 + t * 32 + b) * 128 + ci]);
                        acc = fmaf(wk[ky * 3 + kx], sp, acc);
                    }
                }
            }
            const float invd = gamma[co] / sqrtf(var[co] + 1e-5f);
            const float bias = beta[co] - mean[co] * invd;
            y = acc * invd + bias;
        }
        float v = 0.f;
#pragma unroll
        for (int t = 0; t < T_STEPS; t++) {
            float yt = __shfl_sync(0xffffffffu, y, t);
            v += yt;
            float s = (v >= 1.f) ? 1.f : 0.f;
            v *= (1.f - s);
            if (lane == t)
                out[((size_t)p * 256 + t * 32 + b) * 128 + co] = __float2bfloat16(s);
        }
    }
}

// ------------------------- conv 3x3 + BN via mma.sync -----------------------
template<int S>
__global__ void __launch_bounds__(256, 1)
conv_mma_kernel(const __nv_bfloat16* __restrict__ spk, const __nv_bfloat16* __restrict__ wp,
                const float* __restrict__ gamma, const float* __restrict__ beta,
                const float* __restrict__ mean,  const float* __restrict__ var,
                float* __restrict__ out) {
    extern __shared__ char dsm[];
    const int tid = threadIdx.x, lane = tid & 31, wid = tid >> 5;
    const int x0 = blockIdx.x * 4, y = blockIdx.y, tbq = blockIdx.z;
    const int m0w = (wid & 3) * 32, n0w = (wid >> 2) * 32;

    uint32_t raw = smem_u32(dsm);
    uint32_t sb  = (raw + 1023) & ~1023u;
    char* sp = dsm + (sb - raw);
    char* bP = sp;                 // 4 x 16KB B tiles
    char* aP = sp + 65536;         // 32KB A tile
    const uint32_t bBu = sb, aBu = sb + 65536;

    float acc[4][2][4][4];
#pragma unroll
    for (int px = 0; px < 4; px++)
#pragma unroll
        for (int mt = 0; mt < 2; mt++)
#pragma unroll
            for (int nt = 0; nt < 4; nt++)
#pragma unroll
                for (int e = 0; e < 4; e++) acc[px][mt][nt][e] = 0.f;

    for (int k = 0; k < 9; k++) {
        const int dy = k / 3 - 1, dx = k % 3 - 1;
        const int yy = y + dy;
        if (yy < 0 || yy >= 32) continue;
        bool v[4]; int pp[4];
#pragma unroll
        for (int px = 0; px < 4; px++) {
            int xx = x0 + px + dx;
            v[px] = (xx >= 0 && xx < 32);
            pp[px] = yy * 32 + xx;
        }
        __syncthreads();
#pragma unroll
        for (int px = 0; px < 4; px++) if (v[px]) {
            const uint4* g = (const uint4*)spk + ((size_t)pp[px] * 256 + tbq * 64) * 16;
#pragma unroll
            for (int ps = 0; ps < 4; ps++) {
                int vi = ps * 256 + tid;
                *(uint4*)(bP + px * 16384 + soff(vi >> 4, vi & 15)) = __ldg(&g[vi]);
            }
        }
        {
            const uint4* g = (const uint4*)wp + (size_t)(k * S) * 2048;
#pragma unroll
            for (int ps = 0; ps < 8; ps++) {
                int vi = ps * 256 + tid;
                *(uint4*)(aP + soff(vi >> 4, vi & 15)) = __ldg(&g[vi]);
            }
        }
        __syncthreads();

        for (int s = 0;;) {
#pragma unroll
            for (int j = 0; j < 8; j++) {
                uint32_t a[2][4];
#pragma unroll
                for (int mt = 0; mt < 2; mt++) {
                    int row = m0w + mt * 16 + (lane & 15);
                    ldsm4(a[mt], aBu + soff(row, 2 * j + (lane >> 4)));
                }
#pragma unroll
                for (int px = 0; px < 4; px++) if (v[px]) {
                    uint32_t b[2][4];
#pragma unroll
                    for (int q = 0; q < 2; q++) {
                        int row = n0w + q * 16 + ((lane >> 4) << 3) + (lane & 7);
                        ldsm4(b[q], bBu + px * 16384 + soff(row, 2 * j + ((lane >> 3) & 1)));
                    }
#pragma unroll
                    for (int mt = 0; mt < 2; mt++)
#pragma unroll
                        for (int q = 0; q < 2; q++)
#pragma unroll
                            for (int t = 0; t < 2; t++)
                                mma16816(acc[px][mt][q * 2 + t], a[mt], b[q][t * 2], b[q][t * 2 + 1]);
                }
            }
            if (++s >= S) break;
            __syncthreads();
            const uint4* g = (const uint4*)wp + (size_t)(k * S + s) * 2048;
#pragma unroll
            for (int ps = 0; ps < 8; ps++) {
                int vi = ps * 256 + tid;
                *(uint4*)(aP + soff(vi >> 4, vi & 15)) = __ldg(&g[vi]);
            }
            __syncthreads();
        }
    }

    const int lr = lane >> 2, lc = (lane & 3) * 2;
    float iv[2][2], bv[2][2];
#pragma unroll
    for (int mt = 0; mt < 2; mt++)
#pragma unroll
        for (int h = 0; h < 2; h++) {
            int co = m0w + mt * 16 + h * 8 + lr;
            float z = gamma[co] / sqrtf(var[co] + EPS);
            iv[mt][h] = z;
            bv[mt][h] = beta[co] - mean[co] * z;
        }
#pragma unroll
    for (int px = 0; px < 4; px++) {
        float* bas = out + (((size_t)(y * 32 + x0 + px) * 256) + tbq * 64) * 128;
#pragma unroll
        for (int mt = 0; mt < 2; mt++) {
            const int co = m0w + mt * 16 + lr;
#pragma unroll
            for (int nt = 0; nt < 4; nt++) {
                const int n = n0w + nt * 8 + lc;
                float* o = bas + (size_t)n * 128 + co;
                o[0]   = acc[px][mt][nt][0] * iv[mt][0] + bv[mt][0];
                o[128] = acc[px][mt][nt][1] * iv[mt][0] + bv[mt][0];
                o[8]   = acc[px][mt][nt][2] * iv[mt][1] + bv[mt][1];
                o[136] = acc[px][mt][nt][3] * iv[mt][1] + bv[mt][1];
            }
        }
    }
}

// ------------------------- final transpose: [p][tb][co] -> NCHW -------------
__global__ void transpose_kernel(const float* __restrict__ in, float* __restrict__ out) {
    __shared__ float sm[32][33];
    const int pt = blockIdx.x * 32, ct = blockIdx.y * 32, tb = blockIdx.z;
    const int i = threadIdx.x >> 5, j = threadIdx.x & 31;
#pragma unroll
    for (int r = 0; r < 4; r++) {
        int p = i + r * 8;
        sm[p][j] = in[((size_t)(pt + p) * 256 + tb) * 128 + ct + j];
    }
    __syncthreads();
#pragma unroll
    for (int r = 0; r < 4; r++) {
        int c = i + r * 8;
        out[((size_t)tb * 128 + ct + c) * 1024 + pt + j] = sm[j][c];
    }
}

// ------------------------- pipeline -----------------------------------------
extern "C" void kernel_launch(void* const* d_in, const int* in_sizes, int n_in,
                              void* d_out, int out_size) {
    const float* x  = (const float*)d_in[0];
    const float* w1 = (const float*)d_in[1];
    const float* g1 = (const float*)d_in[2];
    const float* b1 = (const float*)d_in[3];
    const float* m1 = (const float*)d_in[4];
    const float* v1 = (const float*)d_in[5];
    const float* w2 = (const float*)d_in[6];
    const float* g2 = (const float*)d_in[7];
    const float* b2 = (const float*)d_in[8];
    const float* m2 = (const float*)d_in[9];
    const float* v2 = (const float*)d_in[10];
    float* out = (float*)d_out;

    __nv_bfloat16 *spk, *spk2, *w1p, *w2p; float* mid;
    cudaGetSymbolAddress((void**)&spk,  g_spk);
    cudaGetSymbolAddress((void**)&spk2, g_spk2);
    cudaGetSymbolAddress((void**)&mid,  g_mid);
    cudaGetSymbolAddress((void**)&w1p,  g_w1p);
    cudaGetSymbolAddress((void**)&w2p,  g_w2p);

    const int SMEM = 4 * 16384 + 32768 + 1024;    // 99328
    cudaFuncSetAttribute(conv_mma_kernel<3>, cudaFuncAttributeMaxDynamicSharedMemorySize, SMEM);
    cudaFuncSetAttribute(conv_mma_kernel<2>, cudaFuncAttributeMaxDynamicSharedMemorySize, SMEM);

    wprep_kernel<3><<<(9 * 128 * 128 + 255) / 256, 256>>>(w1, w1p);
    wprep_kernel<2><<<(9 * 128 * 128 + 255) / 256, 256>>>(w2, w2p);
    zero_flag_kernel<<<1, 32>>>();

    if1_kernel<<<dim3(32, 4, 32), 1024>>>(x, spk);

    dim3 cgrid(8, 32, 4);
    conv_mma_kernel<3><<<cgrid, 256, SMEM>>>(spk, w1p, g1, b1, m1, v1, mid);
    if2_flag_kernel<<<NELEM / 256, 256>>>(mid, spk2);
    fix_kernel<<<4096, 128>>>(spk, w1, g1, b1, m1, v1, spk2);
    conv_mma_kernel<2><<<cgrid, 256, SMEM>>>(spk2, w2p, g2, b2, m2, v2, mid);

    transpose_kernel<<<dim3(32, 4, 256), 256>>>(mid, out);
}

// round 14
// speedup vs baseline: 1.7242x; 1.1274x over previous
#include <cuda_runtime.h>
#include <cuda_bf16.h>
#include <math.h>
#include <stdint.h>

#define T_STEPS 8
#define CH      128
#define PLANE   1024
#define NELEM   (32 * CH * PLANE)          // 4,194,304
#define TOTAL   (T_STEPS * NELEM)          // 33,554,432
#define EPS     1e-5f
#define DELTA   3e-3f                      // IF2 near-threshold flag window
#define FLAGCAP (1 << 21)

// Scratch (no cudaMalloc allowed)
__device__ __align__(16) __nv_bfloat16 g_spk[TOTAL];           // IF1 spikes [p][tb][ci]
__device__ __align__(16) __nv_bfloat16 g_spk2[TOTAL];          // IF2 spikes [p][tb][ci]
__device__ __align__(16) float         g_mid[TOTAL];           // conv1 out [p][tb][co]
__device__ __align__(16) __nv_bfloat16 g_w1p[18 * 128 * 128];  // conv1 2-split [k*2+s][co][ci]
__device__ __align__(16) __nv_bfloat16 g_w2p[18 * 128 * 128];  // conv2 2-split [k*2+s][co][ci]
__device__ unsigned int g_flags[FLAGCAP];
__device__ unsigned int g_nflag;

// ------------------------- helpers -----------------------------------------
__device__ __forceinline__ uint32_t smem_u32(const void* p) {
    uint32_t a;
    asm("{ .reg .u64 t; cvta.to.shared.u64 t, %1; cvt.u32.u64 %0, t; }" : "=r"(a) : "l"(p));
    return a;
}
__device__ __forceinline__ void ldsm4(uint32_t* r, uint32_t a) {
    asm volatile("ldmatrix.sync.aligned.m8n8.x4.shared.b16 {%0,%1,%2,%3}, [%4];"
                 : "=r"(r[0]), "=r"(r[1]), "=r"(r[2]), "=r"(r[3]) : "r"(a));
}
__device__ __forceinline__ void mma16816(float* d, const uint32_t* a, uint32_t b0, uint32_t b1) {
    asm volatile(
        "mma.sync.aligned.m16n8k16.row.col.f32.bf16.bf16.f32 "
        "{%0,%1,%2,%3}, {%4,%5,%6,%7}, {%8,%9}, {%0,%1,%2,%3};"
        : "+f"(d[0]), "+f"(d[1]), "+f"(d[2]), "+f"(d[3])
        : "r"(a[0]), "r"(a[1]), "r"(a[2]), "r"(a[3]), "r"(b0), "r"(b1));
}
// XOR-swizzled offset in a [rows x 128ci] bf16 tile (256B rows, 16B chunks)
__device__ __forceinline__ uint32_t soff(int row, int ch) {
    return (uint32_t)(row * 256 + ((ch ^ (row & 7)) << 4));
}

// ------------------------- weight split (2 bf16 residuals) ------------------
__global__ void wprep_kernel(const float* __restrict__ w, __nv_bfloat16* __restrict__ wp) {
    int idx = blockIdx.x * 256 + threadIdx.x;          // 9*128*128
    if (idx >= 9 * 128 * 128) return;
    int ci = idx & 127, co = (idx >> 7) & 127, k = idx >> 14;
    float v = w[((size_t)co * 128 + ci) * 9 + k];
#pragma unroll
    for (int s = 0; s < 2; s++) {
        __nv_bfloat16 h = __float2bfloat16(v);
        wp[(((size_t)k * 2 + s) * 128 + co) * 128 + ci] = h;
        v -= __bfloat162float(h);
    }
}

// ------------------------- IF1: NCHW fp32 -> [p][tb][ci] bf16 ---------------
__global__ void if1_kernel(const float* __restrict__ x, __nv_bfloat16* __restrict__ out) {
    __shared__ __nv_bfloat16 sm[32][34];
    const int p0 = blockIdx.x * 32, ci0 = blockIdx.y * 32, b = blockIdx.z;
    const int i = threadIdx.x >> 5, j = threadIdx.x & 31;
    const float* xp = x + ((size_t)b * CH + ci0 + i) * PLANE + p0 + j;
    float v = 0.f;
#pragma unroll
    for (int t = 0; t < T_STEPS; t++) {
        v += xp[(size_t)t * NELEM];
        float s = (v >= 1.f) ? 1.f : 0.f;
        v *= (1.f - s);
        __syncthreads();
        sm[j][i] = __float2bfloat16(s);
        __syncthreads();
        out[((size_t)(p0 + i) * 256 + t * 32 + b) * 128 + ci0 + j] = sm[i][j];
    }
}

// ------------------------- IF2 + near-threshold flagging --------------------
__global__ void zero_flag_kernel() {
    if (threadIdx.x == 0 && blockIdx.x == 0) g_nflag = 0;
}
__global__ void if2_flag_kernel(const float* __restrict__ in, __nv_bfloat16* __restrict__ out) {
    size_t idx = (size_t)blockIdx.x * 256 + threadIdx.x;
    int co = (int)(idx & 127);
    int b  = (int)((idx >> 7) & 31);
    size_t p = idx >> 12;
    float v = 0.f;
    bool near = false;
#pragma unroll
    for (int t = 0; t < T_STEPS; t++) {
        size_t off = (p * 256 + (size_t)t * 32 + b) * 128 + co;
        v += in[off];
        near |= (fabsf(v - 1.f) < DELTA);
        float s = (v >= 1.f) ? 1.f : 0.f;
        v *= (1.f - s);
        out[off] = __float2bfloat16(s);
    }
    if (near) {
        unsigned int id = atomicAdd(&g_nflag, 1u);
        if (id < FLAGCAP) g_flags[id] = ((unsigned)p << 12) | ((unsigned)b << 7) | (unsigned)co;
    }
}

// ------------------------- flip correction ----------------------------------
// One warp per flagged neuron; lanes 0-7 recompute conv1+BN (t=lane) in the
// exact FFMA2-reference order (ci ascending, taps row-major), rescan, rewrite.
__global__ void __launch_bounds__(128)
fix_kernel(const __nv_bfloat16* __restrict__ spk, const float* __restrict__ wgt,
           const float* __restrict__ gamma, const float* __restrict__ beta,
           const float* __restrict__ mean,  const float* __restrict__ var,
           __nv_bfloat16* __restrict__ out) {
    const unsigned int n = min(g_nflag, (unsigned)FLAGCAP);
    const int lane = threadIdx.x & 31;
    const int gw = (blockIdx.x * 128 + threadIdx.x) >> 5;
    for (unsigned int i = gw; i < n; i += 4096 * 4) {
        const unsigned int f = g_flags[i];
        const int co = f & 127, b = (f >> 7) & 31, p = f >> 12;
        const int h = p >> 5, w = p & 31;
        float y = 0.f;
        if (lane < 8) {
            const int t = lane;
            float acc = 0.f;
            for (int ci = 0; ci < 128; ci++) {
                const float* wk = wgt + ((size_t)co * 128 + ci) * 9;
#pragma unroll
                for (int ky = 0; ky < 3; ky++) {
                    const int yy = h + ky - 1;
                    if (yy < 0 || yy >= 32) continue;
#pragma unroll
                    for (int kx = 0; kx < 3; kx++) {
                        const int xx = w + kx - 1;
                        if (xx < 0 || xx >= 32) continue;
                        float sp = __bfloat162float(
                            spk[((size_t)(yy * 32 + xx) * 256 + t * 32 + b) * 128 + ci]);
                        acc = fmaf(wk[ky * 3 + kx], sp, acc);
                    }
                }
            }
            const float invd = gamma[co] / sqrtf(var[co] + 1e-5f);
            const float bias = beta[co] - mean[co] * invd;
            y = acc * invd + bias;
        }
        float v = 0.f;
#pragma unroll
        for (int t = 0; t < T_STEPS; t++) {
            float yt = __shfl_sync(0xffffffffu, y, t);
            v += yt;
            float s = (v >= 1.f) ? 1.f : 0.f;
            v *= (1.f - s);
            if (lane == t)
                out[((size_t)p * 256 + t * 32 + b) * 128 + co] = __float2bfloat16(s);
        }
    }
}

// ------------------------- conv 3x3 + BN via mma.sync -----------------------
// Grid (xo=8, y=32, tbq=4), block 256, 1 CTA/SM. 2 weight splits.
// Per dy-row: stage 6 B tiles once (zero-filled OOB -> branch-free MMAs);
// A double-buffered with register prefetch. MODE 0: [p][tb][co]; 1: NCHW.
#define SMEMC (6 * 16384 + 2 * 32768 + 1024)
template<int MODE>
__global__ void __launch_bounds__(256, 1)
conv_mma_kernel(const __nv_bfloat16* __restrict__ spk, const __nv_bfloat16* __restrict__ wp,
                const float* __restrict__ gamma, const float* __restrict__ beta,
                const float* __restrict__ mean,  const float* __restrict__ var,
                float* __restrict__ out) {
    extern __shared__ char dsm[];
    const int tid = threadIdx.x, lane = tid & 31, wid = tid >> 5;
    const int x0 = blockIdx.x * 4, y = blockIdx.y, tbq = blockIdx.z;
    const int m0w = (wid & 3) * 32, n0w = (wid >> 2) * 32;

    uint32_t raw = smem_u32(dsm);
    uint32_t sb  = (raw + 1023) & ~1023u;
    char* sp = dsm + (sb - raw);
    char* bP = sp;                     // 6 x 16KB B tiles
    char* aP = sp + 6 * 16384;         // 2 x 32KB A double buffer
    const uint32_t bBu = sb, aBu = sb + 6 * 16384;

    float acc[4][2][4][4];
#pragma unroll
    for (int px = 0; px < 4; px++)
#pragma unroll
        for (int mt = 0; mt < 2; mt++)
#pragma unroll
            for (int nt = 0; nt < 4; nt++)
#pragma unroll
                for (int e = 0; e < 4; e++) acc[px][mt][nt][e] = 0.f;

    for (int dyi = 0; dyi < 3; dyi++) {
        const int yy = y + dyi - 1;
        if (yy < 0 || yy >= 32) continue;        // uniform, rare

        __syncthreads();   // prior-iteration reads complete before restage
        // Stage 6 B tiles: source pixels x0-1 .. x0+4, zero-filled when OOB.
#pragma unroll
        for (int bx = 0; bx < 6; bx++) {
            const int xx = x0 + bx - 1;
            char* dst = bP + bx * 16384;
            if (xx >= 0 && xx < 32) {
                const uint4* g = (const uint4*)spk + ((size_t)(yy * 32 + xx) * 256 + tbq * 64) * 16;
#pragma unroll
                for (int ps = 0; ps < 4; ps++) {
                    int vi = ps * 256 + tid;
                    *(uint4*)(dst + soff(vi >> 4, vi & 15)) = __ldg(&g[vi]);
                }
            } else {
#pragma unroll
                for (int ps = 0; ps < 4; ps++) {
                    int vi = ps * 256 + tid;
                    *(uint4*)(dst + soff(vi >> 4, vi & 15)) = make_uint4(0, 0, 0, 0);
                }
            }
        }
        // Stage A(idx=0): k = dyi*3 + 0, split 0 -> buffer 0.
        {
            const uint4* g = (const uint4*)wp + (size_t)(dyi * 3 * 2) * 2048;
#pragma unroll
            for (int ps = 0; ps < 8; ps++) {
                int vi = ps * 256 + tid;
                *(uint4*)(aP + soff(vi >> 4, vi & 15)) = __ldg(&g[vi]);
            }
        }
        __syncthreads();

        for (int idx = 0; idx < 6; idx++) {       // idx = dxi*2 + s
            const int dxi = idx >> 1;
            // Prefetch next A tile into registers (hidden under MMA burst).
            uint4 pf[8];
            if (idx < 5) {
                const uint4* g = (const uint4*)wp + (size_t)((dyi * 3) * 2 + idx + 1) * 2048;
#pragma unroll
                for (int ps = 0; ps < 8; ps++) pf[ps] = __ldg(&g[ps * 256 + tid]);
            }

            const uint32_t aB = aBu + (idx & 1) * 32768;
#pragma unroll
            for (int j = 0; j < 8; j++) {
                uint32_t a[2][4];
#pragma unroll
                for (int mt = 0; mt < 2; mt++)
                    ldsm4(a[mt], aB + soff(m0w + mt * 16 + (lane & 15), 2 * j + (lane >> 4)));
#pragma unroll
                for (int px = 0; px < 4; px++) {
                    const uint32_t bT = bBu + (px + dxi) * 16384;
                    uint32_t b[2][4];
#pragma unroll
                    for (int q = 0; q < 2; q++)
                        ldsm4(b[q], bT + soff(n0w + q * 16 + ((lane >> 4) << 3) + (lane & 7),
                                              2 * j + ((lane >> 3) & 1)));
#pragma unroll
                    for (int mt = 0; mt < 2; mt++)
#pragma unroll
                        for (int q = 0; q < 2; q++)
#pragma unroll
                            for (int t = 0; t < 2; t++)
                                mma16816(acc[px][mt][q * 2 + t], a[mt], b[q][t * 2], b[q][t * 2 + 1]);
                }
            }

            if (idx < 5) {
                char* dst = aP + ((idx + 1) & 1) * 32768;
#pragma unroll
                for (int ps = 0; ps < 8; ps++) {
                    int vi = ps * 256 + tid;
                    *(uint4*)(dst + soff(vi >> 4, vi & 15)) = pf[ps];
                }
                __syncthreads();
            }
        }
    }

    // Epilogue: BN + store.
    const int lr = lane >> 2, lc = (lane & 3) * 2;
    float iv[2][2], bv[2][2];
#pragma unroll
    for (int mt = 0; mt < 2; mt++)
#pragma unroll
        for (int h = 0; h < 2; h++) {
            int co = m0w + mt * 16 + h * 8 + lr;
            float z = gamma[co] / sqrtf(var[co] + EPS);
            iv[mt][h] = z;
            bv[mt][h] = beta[co] - mean[co] * z;
        }
    if (MODE == 0) {
#pragma unroll
        for (int px = 0; px < 4; px++) {
            float* bas = out + (((size_t)(y * 32 + x0 + px) * 256) + tbq * 64) * 128;
#pragma unroll
            for (int mt = 0; mt < 2; mt++) {
                const int co = m0w + mt * 16 + lr;
#pragma unroll
                for (int nt = 0; nt < 4; nt++) {
                    const int n = n0w + nt * 8 + lc;
                    float* o = bas + (size_t)n * 128 + co;
                    o[0]   = acc[px][mt][nt][0] * iv[mt][0] + bv[mt][0];
                    o[128] = acc[px][mt][nt][1] * iv[mt][0] + bv[mt][0];
                    o[8]   = acc[px][mt][nt][2] * iv[mt][1] + bv[mt][1];
                    o[136] = acc[px][mt][nt][3] * iv[mt][1] + bv[mt][1];
                }
            }
        }
    } else {
        // NCHW: out[((tb*128+co)*1024) + y*32 + x], float4 over px (x0 % 4 == 0).
        const int pbase = y * 32 + x0;
#pragma unroll
        for (int mt = 0; mt < 2; mt++) {
            const int co = m0w + mt * 16 + lr;
#pragma unroll
            for (int nt = 0; nt < 4; nt++) {
                const int n = tbq * 64 + n0w + nt * 8 + lc;
#pragma unroll
                for (int e = 0; e < 4; e++) {
                    const int cc = co + (e >> 1) * 8;
                    const int nn = n + (e & 1);
                    const float z = iv[mt][e >> 1], bb = bv[mt][e >> 1];
                    float4 v = make_float4(acc[0][mt][nt][e] * z + bb,
                                           acc[1][mt][nt][e] * z + bb,
                                           acc[2][mt][nt][e] * z + bb,
                                           acc[3][mt][nt][e] * z + bb);
                    *(float4*)(out + ((size_t)nn * 128 + cc) * 1024 + pbase) = v;
                }
            }
        }
    }
}

// ------------------------- pipeline -----------------------------------------
extern "C" void kernel_launch(void* const* d_in, const int* in_sizes, int n_in,
                              void* d_out, int out_size) {
    const float* x  = (const float*)d_in[0];
    const float* w1 = (const float*)d_in[1];
    const float* g1 = (const float*)d_in[2];
    const float* b1 = (const float*)d_in[3];
    const float* m1 = (const float*)d_in[4];
    const float* v1 = (const float*)d_in[5];
    const float* w2 = (const float*)d_in[6];
    const float* g2 = (const float*)d_in[7];
    const float* b2 = (const float*)d_in[8];
    const float* m2 = (const float*)d_in[9];
    const float* v2 = (const float*)d_in[10];
    float* out = (float*)d_out;

    __nv_bfloat16 *spk, *spk2, *w1p, *w2p; float* mid;
    cudaGetSymbolAddress((void**)&spk,  g_spk);
    cudaGetSymbolAddress((void**)&spk2, g_spk2);
    cudaGetSymbolAddress((void**)&mid,  g_mid);
    cudaGetSymbolAddress((void**)&w1p,  g_w1p);
    cudaGetSymbolAddress((void**)&w2p,  g_w2p);

    cudaFuncSetAttribute(conv_mma_kernel<0>, cudaFuncAttributeMaxDynamicSharedMemorySize, SMEMC);
    cudaFuncSetAttribute(conv_mma_kernel<1>, cudaFuncAttributeMaxDynamicSharedMemorySize, SMEMC);

    wprep_kernel<<<(9 * 128 * 128 + 255) / 256, 256>>>(w1, w1p);
    wprep_kernel<<<(9 * 128 * 128 + 255) / 256, 256>>>(w2, w2p);
    zero_flag_kernel<<<1, 32>>>();

    if1_kernel<<<dim3(32, 4, 32), 1024>>>(x, spk);

    dim3 cgrid(8, 32, 4);
    conv_mma_kernel<0><<<cgrid, 256, SMEMC>>>(spk, w1p, g1, b1, m1, v1, mid);
    if2_flag_kernel<<<NELEM / 256, 256>>>(mid, spk2);
    fix_kernel<<<4096, 128>>>(spk, w1, g1, b1, m1, v1, spk2);
    conv_mma_kernel<1><<<cgrid, 256, SMEMC>>>(spk2, w2p, g2, b2, m2, v2, out);
}